// round 6
// baseline (speedup 1.0000x reference)
#include <cuda_runtime.h>
#include <math.h>

#define NL 6
#define B  8
#define T  4
#define L  2048
#define H  16
#define D  64
#define E  1024
#define FF 4096
#define INDIM 32
#define NTOK 32
#define NB 128

#define CACHE_F4 50331648LL            // NL*2*B*L*E/4

// -------- scratch (device globals) --------
__device__ float g_x   [NTOK * E];
__device__ float g_xn  [NTOK * E];
__device__ float g_q   [NTOK * E];
__device__ float g_attn[NTOK * E];
__device__ float g_h   [NTOK * FF];
__device__ float g_part[262144];           // split-K partials (max 8*32*1024 / 2*32*4096)
__device__ int                g_bar_count = 0;
__device__ volatile unsigned  g_bar_epoch = 0;

// -------- shared memory overlays --------
struct SG { float Ws[64][36]; unsigned long long XsP[16][33]; };      // ~13.4 KB
struct SA { float qs[4][64]; float sc[4][1056]; float red[8];
            float inv[4]; float vpart[4][4][64]; };                   // ~22 KB
#define SMEM_BYTES (sizeof(SA) > sizeof(SG) ? sizeof(SA) : sizeof(SG))

// -------- f32x2 helpers --------
__device__ __forceinline__ unsigned long long pk2(float lo, float hi) {
    unsigned long long r;
    asm("mov.b64 %0, {%1, %2};" : "=l"(r) : "f"(lo), "f"(hi));
    return r;
}
__device__ __forceinline__ void fma2(unsigned long long& d,
                                     unsigned long long a,
                                     unsigned long long b) {
    asm("fma.rn.f32x2 %0, %1, %2, %3;" : "=l"(d) : "l"(a), "l"(b), "l"(d));
}
__device__ __forceinline__ float2 upk(unsigned long long v) {
    float2 f;
    asm("mov.b64 {%0, %1}, %2;" : "=f"(f.x), "=f"(f.y) : "l"(v));
    return f;
}

// -------- grid barrier (epoch-based; safe across graph replays) --------
__device__ __forceinline__ void gbar(unsigned target)
{
    __syncthreads();
    if (threadIdx.x == 0) {
        __threadfence();
        int v = atomicAdd(&g_bar_count, 1);
        if (v == NB - 1) {
            atomicExch(&g_bar_count, 0);
            __threadfence();
            g_bar_epoch = target;
        } else {
            while ((int)(g_bar_epoch - target) < 0) __nanosleep(64);
        }
        __threadfence();
    }
    __syncthreads();
}

// -------- GEMM tile: 64 cols x 32 rows, Kc chunk of K, f32x2 --------
__device__ void gemv_tile(const float* __restrict__ X,
                          const float* __restrict__ W,
                          float* __restrict__ part,
                          int K, int N, int n0, int kbase, int Kc, int ks,
                          SG* sg)
{
    const int t    = threadIdx.x;
    const int lane = t & 31;
    const int c0   = (t >> 5) * 8;
    const int nch  = Kc >> 5;
    const int xrow = t >> 3, xk = (t & 7) * 4;
    const int wrow = t >> 2, wk = (t & 3) * 8;

    const float4* xg = (const float4*)(X + (size_t)xrow * K + kbase + xk);
    const float4* wg = (const float4*)(W + (size_t)(n0 + wrow) * K + kbase + wk);
    float4 xr  = *xg;
    float4 wr0 = wg[0];
    float4 wr1 = wg[1];

    unsigned long long acc[8];
    #pragma unroll
    for (int c = 0; c < 8; c++) acc[c] = 0ULL;

    for (int ch = 0; ch < nch; ch++) {
        sg->XsP[(xk >> 1)    ][xrow] = pk2(xr.x, xr.y);
        sg->XsP[(xk >> 1) + 1][xrow] = pk2(xr.z, xr.w);
        *(float4*)&sg->Ws[wrow][wk]     = wr0;
        *(float4*)&sg->Ws[wrow][wk + 4] = wr1;
        __syncthreads();
        if (ch + 1 < nch) { xg += 8; wg += 8; xr = *xg; wr0 = wg[0]; wr1 = wg[1]; }

        #pragma unroll
        for (int k2 = 0; k2 < 16; k2 += 2) {
            unsigned long long x0 = sg->XsP[k2][lane];
            unsigned long long x1 = sg->XsP[k2 + 1][lane];
            #pragma unroll
            for (int c = 0; c < 8; c++) {
                longlong2 w = *(const longlong2*)&sg->Ws[c0 + c][k2 * 2];
                fma2(acc[c], x0, (unsigned long long)w.x);
                fma2(acc[c], x1, (unsigned long long)w.y);
            }
        }
        __syncthreads();
    }

    float* pp = part + ((size_t)ks * 32 + lane) * N + n0 + c0;
    #pragma unroll
    for (int c = 0; c < 8; c++) {
        float2 p = upk(acc[c]);
        pp[c] = p.x + p.y;
    }
}

// -------- LN helpers (one block per token; red = 8 floats smem) --------
__device__ void ln_body(const float v[4], float* red, float* mean_o, float* r_o)
{
    int tid = threadIdx.x;
    float s = v[0] + v[1] + v[2] + v[3];
    #pragma unroll
    for (int o = 16; o > 0; o >>= 1) s += __shfl_xor_sync(0xffffffffu, s, o);
    if ((tid & 31) == 0) red[tid >> 5] = s;
    __syncthreads();
    float mean = (red[0]+red[1]+red[2]+red[3]+red[4]+red[5]+red[6]+red[7]) * (1.0f / E);
    float s2 = 0.f;
    #pragma unroll
    for (int j = 0; j < 4; j++) { float d = v[j] - mean; s2 += d * d; }
    #pragma unroll
    for (int o = 16; o > 0; o >>= 1) s2 += __shfl_xor_sync(0xffffffffu, s2, o);
    __syncthreads();
    if ((tid & 31) == 0) red[tid >> 5] = s2;
    __syncthreads();
    float var = (red[0]+red[1]+red[2]+red[3]+red[4]+red[5]+red[6]+red[7]) * (1.0f / E);
    *mean_o = mean;
    *r_o = rsqrtf(var + 1e-5f);
}

__device__ void ln_phase(const float* __restrict__ x,
                         const float* __restrict__ w,
                         const float* __restrict__ b,
                         float* __restrict__ y, float* red)
{
    int tid = threadIdx.x;
    float v[4];
    #pragma unroll
    for (int j = 0; j < 4; j++) v[j] = x[tid + 256 * j];
    float mean, r;
    ln_body(v, red, &mean, &r);
    #pragma unroll
    for (int j = 0; j < 4; j++) {
        int idx = tid + 256 * j;
        y[idx] = (v[j] - mean) * r * w[idx] + b[idx];
    }
}

// reduce KS split-K partials + residual add into x, then LN -> xn
template<int KS>
__device__ void reduce_add_ln(const float* __restrict__ part, int tok,
                              float* __restrict__ x,
                              const float* __restrict__ w,
                              const float* __restrict__ b,
                              float* __restrict__ xn, float* red)
{
    int tid = threadIdx.x;
    float v[4];
    #pragma unroll
    for (int j = 0; j < 4; j++) {
        int idx = tid + 256 * j;
        float p = 0.f;
        #pragma unroll
        for (int k = 0; k < KS; k++) p += part[((size_t)(k * 32 + tok)) * E + idx];
        float xv = x[(size_t)tok * E + idx] + p;
        x[(size_t)tok * E + idx] = xv;
        v[j] = xv;
    }
    float mean, r;
    ln_body(v, red, &mean, &r);
    #pragma unroll
    for (int j = 0; j < 4; j++) {
        int idx = tid + 256 * j;
        xn[(size_t)tok * E + idx] = (v[j] - mean) * r * w[idx] + b[idx];
    }
}

// final: reduce + add + LN + eos dot
__device__ void reduce_add_ln_eos(const float* __restrict__ part, int tok,
                                  float* __restrict__ x,
                                  const float* __restrict__ w,
                                  const float* __restrict__ b,
                                  const float* __restrict__ ew,
                                  const float* __restrict__ eb,
                                  float* __restrict__ out_x,
                                  float* __restrict__ out_eos, float* red)
{
    int tid = threadIdx.x;
    float v[4];
    #pragma unroll
    for (int j = 0; j < 4; j++) {
        int idx = tid + 256 * j;
        float p = 0.f;
        #pragma unroll
        for (int k = 0; k < 8; k++) p += part[((size_t)(k * 32 + tok)) * E + idx];
        v[j] = x[(size_t)tok * E + idx] + p;
    }
    float mean, r;
    ln_body(v, red, &mean, &r);
    float ed = 0.f;
    #pragma unroll
    for (int j = 0; j < 4; j++) {
        int idx = tid + 256 * j;
        float y = (v[j] - mean) * r * w[idx] + b[idx];
        out_x[(size_t)tok * E + idx] = y;
        ed += y * ew[idx];
    }
    #pragma unroll
    for (int o = 16; o > 0; o >>= 1) ed += __shfl_xor_sync(0xffffffffu, ed, o);
    __syncthreads();
    if ((tid & 31) == 0) red[tid >> 5] = ed;
    __syncthreads();
    if (tid == 0)
        out_eos[tok] = red[0]+red[1]+red[2]+red[3]+red[4]+red[5]+red[6]+red[7] + eb[0];
}

// -------- attention: one block per (b,h) --------
__device__ void attn_phase(SA* sa, const float* __restrict__ q,
                           const float* __restrict__ kin,
                           const float* __restrict__ vin,
                           const float* __restrict__ kout,
                           const float* __restrict__ vout,
                           const int* __restrict__ posl,
                           float* __restrict__ outp)
{
    int bh = blockIdx.x;
    int b = bh >> 4, h = bh & 15;
    int tid = threadIdx.x;
    int pos = posl[b];
    int slen = pos + T;

    {
        int t = tid >> 6, d = tid & 63;
        sa->qs[t][d] = q[((size_t)(b * T + t)) * E + h * D + d];
    }
    __syncthreads();

    const float scale = 0.125f;
    for (int s = tid; s < slen; s += 256) {
        size_t off = ((size_t)b * L + s) * E + h * D;
        bool old = (s < pos);
        const float4* kr = (const float4*)((old ? kin : kout) + off);
        float d0 = 0.f, d1 = 0.f, d2 = 0.f, d3 = 0.f;
        #pragma unroll
        for (int i4 = 0; i4 < 16; i4++) {
            float4 kv = kr[i4];
            if (old) {
                kv.x = isnan(kv.x) ? 0.f : kv.x;
                kv.y = isnan(kv.y) ? 0.f : kv.y;
                kv.z = isnan(kv.z) ? 0.f : kv.z;
                kv.w = isnan(kv.w) ? 0.f : kv.w;
            }
            int d = i4 * 4;
            d0 += sa->qs[0][d]*kv.x + sa->qs[0][d+1]*kv.y + sa->qs[0][d+2]*kv.z + sa->qs[0][d+3]*kv.w;
            d1 += sa->qs[1][d]*kv.x + sa->qs[1][d+1]*kv.y + sa->qs[1][d+2]*kv.z + sa->qs[1][d+3]*kv.w;
            d2 += sa->qs[2][d]*kv.x + sa->qs[2][d+1]*kv.y + sa->qs[2][d+2]*kv.z + sa->qs[2][d+3]*kv.w;
            d3 += sa->qs[3][d]*kv.x + sa->qs[3][d+1]*kv.y + sa->qs[3][d+2]*kv.z + sa->qs[3][d+3]*kv.w;
        }
        sa->sc[0][s] = (s <= pos + 0) ? d0 * scale : -1e30f;
        sa->sc[1][s] = (s <= pos + 1) ? d1 * scale : -1e30f;
        sa->sc[2][s] = (s <= pos + 2) ? d2 * scale : -1e30f;
        sa->sc[3][s] = (s <= pos + 3) ? d3 * scale : -1e30f;
    }
    __syncthreads();

    #pragma unroll
    for (int t = 0; t < 4; t++) {
        float m = -1e30f;
        for (int s = tid; s < slen; s += 256) m = fmaxf(m, sa->sc[t][s]);
        #pragma unroll
        for (int o = 16; o > 0; o >>= 1) m = fmaxf(m, __shfl_xor_sync(0xffffffffu, m, o));
        if ((tid & 31) == 0) sa->red[tid >> 5] = m;
        __syncthreads();
        m = fmaxf(fmaxf(fmaxf(sa->red[0], sa->red[1]), fmaxf(sa->red[2], sa->red[3])),
                  fmaxf(fmaxf(sa->red[4], sa->red[5]), fmaxf(sa->red[6], sa->red[7])));
        float ssum = 0.f;
        for (int s = tid; s < slen; s += 256) {
            float e = __expf(sa->sc[t][s] - m);
            sa->sc[t][s] = e;
            ssum += e;
        }
        #pragma unroll
        for (int o = 16; o > 0; o >>= 1) ssum += __shfl_xor_sync(0xffffffffu, ssum, o);
        __syncthreads();
        if ((tid & 31) == 0) sa->red[tid >> 5] = ssum;
        __syncthreads();
        if (tid == 0)
            sa->inv[t] = 1.0f / (sa->red[0]+sa->red[1]+sa->red[2]+sa->red[3]
                               + sa->red[4]+sa->red[5]+sa->red[6]+sa->red[7]);
        __syncthreads();
    }

    {
        int sg = tid >> 6, d = tid & 63;
        int chunk = (slen + 3) >> 2;
        int s0 = sg * chunk;
        int s1 = min(slen, s0 + chunk);
        float a0 = 0.f, a1 = 0.f, a2 = 0.f, a3 = 0.f;
        for (int s = s0; s < s1; s++) {
            bool old = (s < pos);
            float v0 = (old ? vin : vout)[((size_t)b * L + s) * E + h * D + d];
            if (old) v0 = isnan(v0) ? 0.f : v0;
            a0 += sa->sc[0][s] * v0;
            a1 += sa->sc[1][s] * v0;
            a2 += sa->sc[2][s] * v0;
            a3 += sa->sc[3][s] * v0;
        }
        sa->vpart[sg][0][d] = a0;
        sa->vpart[sg][1][d] = a1;
        sa->vpart[sg][2][d] = a2;
        sa->vpart[sg][3][d] = a3;
    }
    __syncthreads();
    {
        int t = tid >> 6, d = tid & 63;
        float sum = sa->vpart[0][t][d] + sa->vpart[1][t][d]
                  + sa->vpart[2][t][d] + sa->vpart[3][t][d];
        outp[((size_t)(b * T + t)) * E + h * D + d] = sum * sa->inv[t];
    }
}

// ======== THE MEGAKERNEL ========
__global__ __launch_bounds__(256) void mega_kernel(
    const float* __restrict__ seq, const float* __restrict__ bos,
    const float* __restrict__ caches, const int* __restrict__ positions,
    const float* __restrict__ in_w, const float* __restrict__ ip_w,
    const float* __restrict__ op_w,
    const float* __restrict__ n1w, const float* __restrict__ n1b,
    const float* __restrict__ n2w, const float* __restrict__ n2b,
    const float* __restrict__ l1w, const float* __restrict__ l2w,
    const float* __restrict__ on_w, const float* __restrict__ on_b,
    const float* __restrict__ eos_w, const float* __restrict__ eos_b,
    float* __restrict__ out_x, float* __restrict__ out_eos,
    float* __restrict__ out_cache, float* __restrict__ out_pos)
{
    __shared__ __align__(16) char smraw[SMEM_BYTES];
    SG* sg = (SG*)smraw;
    SA* sa = (SA*)smraw;
    float* red = (float*)smraw;

    const int bid = blockIdx.x;
    const int tid = threadIdx.x;
    unsigned base = g_bar_epoch;
    unsigned bc = 0;

    // ---- phase: embed (x = clean(seq) @ in_w^T) + out_pos ----
    {
        float* srow = (float*)smraw;               // 32 floats
        int tok = bid >> 2;
        if (tid < 32) {
            float v = seq[tok * INDIM + tid];
            srow[tid] = isnan(v) ? bos[tid] : v;
        }
        __syncthreads();
        int col = ((bid & 3) << 8) + tid;
        const float4* wr = (const float4*)(in_w + (size_t)col * INDIM);
        float acc = 0.f;
        #pragma unroll
        for (int k4 = 0; k4 < 8; k4++) {
            float4 w = wr[k4];
            acc += srow[k4*4]*w.x + srow[k4*4+1]*w.y + srow[k4*4+2]*w.z + srow[k4*4+3]*w.w;
        }
        g_x[(size_t)tok * E + col] = acc;
        if (bid == NB - 1 && tid < NL * B)
            out_pos[tid] = (float)(positions[tid] + T);
    }
    gbar(base + ++bc);

    // ---- phase: ln1 layer 0 ----
    if (bid < NTOK) ln_phase(g_x + (size_t)bid * E, n1w, n1b, g_xn + (size_t)bid * E, red);
    gbar(base + ++bc);

    for (int i = 0; i < NL; i++) {
        const float* ipw = ip_w + (size_t)i * 3 * E * E;
        const float* opw = op_w + (size_t)i * E * E;
        const float* l1  = l1w  + (size_t)i * FF * E;
        const float* l2  = l2w  + (size_t)i * E * FF;
        float* kcache = out_cache + ((size_t)i * 2 + 0) * B * L * E;
        float* vcache = out_cache + ((size_t)i * 2 + 1) * B * L * E;
        const float* kcin = caches + ((size_t)i * 2 + 0) * B * L * E;
        const float* vcin = caches + ((size_t)i * 2 + 1) * B * L * E;
        const int* posl = positions + i * B;

        // qkv gemv: N=3072, ks2 -> 96 units
        if (bid < 96) {
            int tile = bid >> 1, ks = bid & 1;
            gemv_tile(g_xn, ipw, g_part, E, 3 * E, tile * 64, ks * 512, 512, ks, sg);
        }
        gbar(base + ++bc);

        // reduce2 + rope + scatter
        for (int id = bid * 256 + tid; id < 49152; id += NB * 256) {
            int tok = id / 1536;
            int f = (id - tok * 1536) * 2;
            float s0 = g_part[(size_t)tok * 3072 + f]     + g_part[(size_t)(32 + tok) * 3072 + f];
            float s1 = g_part[(size_t)tok * 3072 + f + 1] + g_part[(size_t)(32 + tok) * 3072 + f + 1];
            int b = tok >> 2, t = tok & 3;
            int pos = posl[b];
            if (f < E) {
                int j = (f & 63) >> 1;
                float freq = __expf(-(float)j * (logf(10000.0f) / 32.0f));
                float sn, cs;
                sincosf((float)(pos + t) * freq, &sn, &cs);
                g_q[(size_t)tok * E + f]     = s0 * cs - s1 * sn;
                g_q[(size_t)tok * E + f + 1] = s0 * sn + s1 * cs;
            } else if (f < 2 * E) {
                int fk = f - E;
                int j = (fk & 63) >> 1;
                float freq = __expf(-(float)j * (logf(10000.0f) / 32.0f));
                float sn, cs;
                sincosf((float)(pos + t) * freq, &sn, &cs);
                int slot = (pos + t) % L;
                size_t off = ((size_t)b * L + slot) * E + fk;
                kcache[off]     = s0 * cs - s1 * sn;
                kcache[off + 1] = s0 * sn + s1 * cs;
            } else {
                int fv = f - 2 * E;
                int slot = (pos + t) % L;
                size_t off = ((size_t)b * L + slot) * E + fv;
                vcache[off]     = s0;
                vcache[off + 1] = s1;
            }
        }
        gbar(base + ++bc);

        // attention: block = (b,h)
        attn_phase(sa, g_q, kcin, vcin, kcache, vcache, posl, g_attn);
        gbar(base + ++bc);

        // op gemv: N=1024, ks8 -> 128 units
        {
            int tile = bid >> 3, ks = bid & 7;
            gemv_tile(g_attn, opw, g_part, E, E, tile * 64, ks * 128, 128, ks, sg);
        }
        gbar(base + ++bc);

        // reduce8 + residual + ln2
        if (bid < NTOK)
            reduce_add_ln<8>(g_part, bid, g_x, n2w + (size_t)i * E, n2b + (size_t)i * E, g_xn, red);
        gbar(base + ++bc);

        // l1 gemv: N=4096, ks2 -> 128 units
        {
            int tile = bid >> 1, ks = bid & 1;
            gemv_tile(g_xn, l1, g_part, E, FF, tile * 64, ks * 512, 512, ks, sg);
        }
        gbar(base + ++bc);

        // reduce2 + gelu -> h
        for (int idx = bid * 256 + tid; idx < 32 * FF; idx += NB * 256) {
            float s = g_part[idx] + g_part[32 * FF + idx];
            g_h[idx] = 0.5f * s * (1.0f + erff(s * 0.70710678118654752f));
        }
        gbar(base + ++bc);

        // l2 gemv: K=4096, N=1024, ks8 -> 128 units
        {
            int tile = bid >> 3, ks = bid & 7;
            gemv_tile(g_h, l2, g_part, FF, E, tile * 64, ks * 512, 512, ks, sg);
        }
        gbar(base + ++bc);

        // reduce8 + residual + (ln1 next | final ln + eos)
        if (i + 1 < NL) {
            if (bid < NTOK)
                reduce_add_ln<8>(g_part, bid, g_x,
                                 n1w + (size_t)(i + 1) * E, n1b + (size_t)(i + 1) * E,
                                 g_xn, red);
            gbar(base + ++bc);
        } else {
            if (bid < NTOK)
                reduce_add_ln_eos(g_part, bid, g_x, on_w, on_b,
                                  eos_w, eos_b, out_x, out_eos, red);
        }
    }
}

// -------- bulk cache copy: moderate grid (co-residable), NaN-clean, skip new slots --------
__global__ void cache_copy_kernel(const float4* __restrict__ in,
                                  float4* __restrict__ out,
                                  const int* __restrict__ allpos)
{
    long long stride = (long long)gridDim.x * 256;
    #pragma unroll 4
    for (long long i = (long long)blockIdx.x * 256 + threadIdx.x; i < CACHE_F4; i += stride) {
        unsigned slot = ((unsigned)(i >> 8)) & 2047u;
        unsigned b    = ((unsigned)(i >> 19)) & 7u;
        unsigned l    = ((unsigned)(i >> 22)) >> 1;
        int p = allpos[l * 8 + b];
        if ((unsigned)((int)slot - p) < (unsigned)T) continue;
        float4 v = in[i];
        v.x = isnan(v.x) ? 0.0f : v.x;
        v.y = isnan(v.y) ? 0.0f : v.y;
        v.z = isnan(v.z) ? 0.0f : v.z;
        v.w = isnan(v.w) ? 0.0f : v.w;
        out[i] = v;
    }
}

extern "C" void kernel_launch(void* const* d_in, const int* in_sizes, int n_in,
                              void* d_out, int out_size)
{
    const float* seq       = (const float*)d_in[0];
    const float* bos       = (const float*)d_in[1];
    const float* caches    = (const float*)d_in[2];
    const int*   positions = (const int*)  d_in[3];
    const float* in_w      = (const float*)d_in[4];
    const float* ip_w      = (const float*)d_in[5];
    const float* op_w      = (const float*)d_in[6];
    const float* n1w       = (const float*)d_in[7];
    const float* n1b       = (const float*)d_in[8];
    const float* n2w       = (const float*)d_in[9];
    const float* n2b       = (const float*)d_in[10];
    const float* l1_w      = (const float*)d_in[11];
    const float* l2_w      = (const float*)d_in[12];
    const float* on_w      = (const float*)d_in[13];
    const float* on_b      = (const float*)d_in[14];
    const float* eos_w     = (const float*)d_in[15];
    const float* eos_b     = (const float*)d_in[16];

    float* out = (float*)d_out;
    const size_t cache_elems = (size_t)NL * 2 * B * L * E;
    float* out_x     = out;
    float* out_eos   = out + (size_t)NTOK * E;
    float* out_cache = out_eos + NTOK;
    float* out_pos   = out_cache + cache_elems;

    // ---- fork: copy on side stream, sized to co-reside with the megakernel ----
    cudaStream_t cs;
    cudaStreamCreateWithFlags(&cs, cudaStreamNonBlocking);
    cudaEvent_t evFork, evJoin;
    cudaEventCreateWithFlags(&evFork, cudaEventDisableTiming);
    cudaEventCreateWithFlags(&evJoin, cudaEventDisableTiming);

    cudaEventRecord(evFork, 0);
    cudaStreamWaitEvent(cs, evFork, 0);
    cache_copy_kernel<<<592, 256, 0, cs>>>((const float4*)caches,
                                           (float4*)out_cache, positions);
    cudaEventRecord(evJoin, cs);

    // ---- megakernel: whole network, one launch ----
    mega_kernel<<<NB, 256>>>(seq, bos, caches, positions,
                             in_w, ip_w, op_w,
                             n1w, n1b, n2w, n2b, l1_w, l2_w,
                             on_w, on_b, eos_w, eos_b,
                             out_x, out_eos, out_cache, out_pos);

    cudaStreamWaitEvent(0, evJoin, 0);
}

// round 7
// speedup vs baseline: 1.0064x; 1.0064x over previous
#include <cuda_runtime.h>
#include <math.h>

#define NL 6
#define B  8
#define T  4
#define L  2048
#define H  16
#define D  64
#define E  1024
#define FF 4096
#define INDIM 32
#define NTOK 32
#define NB 128

#define CACHE_F4 50331648LL            // NL*2*B*L*E/4

// -------- scratch (device globals) --------
__device__ float g_x    [NTOK * E];
__device__ float g_xn   [NTOK * E];
__device__ float g_q    [NTOK * E];
__device__ float g_attn [NTOK * E];
__device__ float g_part [262144];      // l1 partials (2 x 32 x 4096)
__device__ float g_part2[262144];      // qkv (2x32x3072) / op / l2 (8x32x1024) partials
__device__ int                g_bar_count = 0;
__device__ volatile unsigned  g_bar_epoch = 0;

// -------- shared memory overlays --------
struct SG { float Ws[64][36]; unsigned long long XsP[16][33]; };
struct SA { float qs[4][64]; float sc[4][1056]; float red[8];
            float inv[4]; float vpart[4][4][64]; };
#define SMEM_BYTES (sizeof(SA) > sizeof(SG) ? sizeof(SA) : sizeof(SG))

// -------- f32x2 helpers --------
__device__ __forceinline__ unsigned long long pk2(float lo, float hi) {
    unsigned long long r;
    asm("mov.b64 %0, {%1, %2};" : "=l"(r) : "f"(lo), "f"(hi));
    return r;
}
__device__ __forceinline__ void fma2(unsigned long long& d,
                                     unsigned long long a,
                                     unsigned long long b) {
    asm("fma.rn.f32x2 %0, %1, %2, %3;" : "=l"(d) : "l"(a), "l"(b), "l"(d));
}
__device__ __forceinline__ float2 upk(unsigned long long v) {
    float2 f;
    asm("mov.b64 {%0, %1}, %2;" : "=f"(f.x), "=f"(f.y) : "l"(v));
    return f;
}
__device__ __forceinline__ float gelu1(float v) {
    return 0.5f * v * (1.0f + erff(v * 0.70710678118654752f));
}

// -------- grid barrier (epoch-based) --------
__device__ __forceinline__ void gbar(unsigned target)
{
    __syncthreads();
    if (threadIdx.x == 0) {
        __threadfence();
        int v = atomicAdd(&g_bar_count, 1);
        if (v == NB - 1) {
            atomicExch(&g_bar_count, 0);
            __threadfence();
            g_bar_epoch = target;
        } else {
            while ((int)(g_bar_epoch - target) < 0) __nanosleep(32);
        }
        __threadfence();
    }
    __syncthreads();
}

// -------- GEMM tile: 64 cols x 32 rows, 2-chunk-deep prefetch, f32x2 --------
// GELU=1: X is two split-K partial buffers (row stride K, second at +32*K);
//         Xeff = gelu(p0+p1) applied on load.
template<int GELU>
__device__ void gemv_tile(const float* __restrict__ X,
                          const float* __restrict__ W,
                          float* __restrict__ part,
                          int K, int N, int n0, int kbase, int Kc, int ks,
                          SG* sg)
{
    const int t    = threadIdx.x;
    const int lane = t & 31;
    const int c0   = (t >> 5) * 8;
    const int nch  = Kc >> 5;
    const int xrow = t >> 3, xk = (t & 7) * 4;
    const int wrow = t >> 2, wk = (t & 3) * 8;

    const float4* xg  = (const float4*)(X + (size_t)xrow * K + kbase + xk);
    const float4* x2g = (const float4*)(X + (size_t)(32 + xrow) * K + kbase + xk);
    const float4* wg  = (const float4*)(W + (size_t)(n0 + wrow) * K + kbase + wk);

    float4 xa = xg[0], xa2, xb, xb2, wa0 = wg[0], wa1 = wg[1], wb0, wb1;
    if (GELU) xa2 = x2g[0];
    if (nch > 1) {
        xb = xg[8]; wb0 = wg[8]; wb1 = wg[9];
        if (GELU) xb2 = x2g[8];
    }

    unsigned long long acc[8];
    #pragma unroll
    for (int c = 0; c < 8; c++) acc[c] = 0ULL;

    for (int ch = 0; ch < nch; ch++) {
        float4 xs, xs2, ws0, ws1;
        if ((ch & 1) == 0) { xs = xa; xs2 = xa2; ws0 = wa0; ws1 = wa1; }
        else               { xs = xb; xs2 = xb2; ws0 = wb0; ws1 = wb1; }
        if (GELU) {
            xs.x = gelu1(xs.x + xs2.x);
            xs.y = gelu1(xs.y + xs2.y);
            xs.z = gelu1(xs.z + xs2.z);
            xs.w = gelu1(xs.w + xs2.w);
        }
        sg->XsP[(xk >> 1)    ][xrow] = pk2(xs.x, xs.y);
        sg->XsP[(xk >> 1) + 1][xrow] = pk2(xs.z, xs.w);
        *(float4*)&sg->Ws[wrow][wk]     = ws0;
        *(float4*)&sg->Ws[wrow][wk + 4] = ws1;
        __syncthreads();

        if (ch + 2 < nch) {
            int off = (ch + 2) * 8;
            if ((ch & 1) == 0) {
                xa = xg[off]; wa0 = wg[off]; wa1 = wg[off + 1];
                if (GELU) xa2 = x2g[off];
            } else {
                xb = xg[off]; wb0 = wg[off]; wb1 = wg[off + 1];
                if (GELU) xb2 = x2g[off];
            }
        }

        #pragma unroll
        for (int k2 = 0; k2 < 16; k2 += 2) {
            unsigned long long x0 = sg->XsP[k2][lane];
            unsigned long long x1 = sg->XsP[k2 + 1][lane];
            #pragma unroll
            for (int c = 0; c < 8; c++) {
                longlong2 w = *(const longlong2*)&sg->Ws[c0 + c][k2 * 2];
                fma2(acc[c], x0, (unsigned long long)w.x);
                fma2(acc[c], x1, (unsigned long long)w.y);
            }
        }
        __syncthreads();
    }

    float* pp = part + ((size_t)ks * 32 + lane) * N + n0 + c0;
    #pragma unroll
    for (int c = 0; c < 8; c++) {
        float2 p = upk(acc[c]);
        pp[c] = p.x + p.y;
    }
}

// -------- LN helpers --------
__device__ void ln_body(const float v[4], float* red, float* mean_o, float* r_o)
{
    int tid = threadIdx.x;
    float s = v[0] + v[1] + v[2] + v[3];
    #pragma unroll
    for (int o = 16; o > 0; o >>= 1) s += __shfl_xor_sync(0xffffffffu, s, o);
    if ((tid & 31) == 0) red[tid >> 5] = s;
    __syncthreads();
    float mean = (red[0]+red[1]+red[2]+red[3]+red[4]+red[5]+red[6]+red[7]) * (1.0f / E);
    float s2 = 0.f;
    #pragma unroll
    for (int j = 0; j < 4; j++) { float d = v[j] - mean; s2 += d * d; }
    #pragma unroll
    for (int o = 16; o > 0; o >>= 1) s2 += __shfl_xor_sync(0xffffffffu, s2, o);
    __syncthreads();
    if ((tid & 31) == 0) red[tid >> 5] = s2;
    __syncthreads();
    float var = (red[0]+red[1]+red[2]+red[3]+red[4]+red[5]+red[6]+red[7]) * (1.0f / E);
    *mean_o = mean;
    *r_o = rsqrtf(var + 1e-5f);
}

__device__ void ln_phase(const float* __restrict__ x,
                         const float* __restrict__ w,
                         const float* __restrict__ b,
                         float* __restrict__ y, float* red)
{
    int tid = threadIdx.x;
    float v[4];
    #pragma unroll
    for (int j = 0; j < 4; j++) v[j] = x[tid + 256 * j];
    float mean, r;
    ln_body(v, red, &mean, &r);
    #pragma unroll
    for (int j = 0; j < 4; j++) {
        int idx = tid + 256 * j;
        y[idx] = (v[j] - mean) * r * w[idx] + b[idx];
    }
}

template<int KS>
__device__ void reduce_add_ln(const float* __restrict__ part, int tok,
                              float* __restrict__ x,
                              const float* __restrict__ w,
                              const float* __restrict__ b,
                              float* __restrict__ xn, float* red)
{
    int tid = threadIdx.x;
    float v[4];
    #pragma unroll
    for (int j = 0; j < 4; j++) {
        int idx = tid + 256 * j;
        float p = 0.f;
        #pragma unroll
        for (int k = 0; k < KS; k++) p += part[((size_t)(k * 32 + tok)) * E + idx];
        float xv = x[(size_t)tok * E + idx] + p;
        x[(size_t)tok * E + idx] = xv;
        v[j] = xv;
    }
    float mean, r;
    ln_body(v, red, &mean, &r);
    #pragma unroll
    for (int j = 0; j < 4; j++) {
        int idx = tid + 256 * j;
        xn[(size_t)tok * E + idx] = (v[j] - mean) * r * w[idx] + b[idx];
    }
}

__device__ void reduce_add_ln_eos(const float* __restrict__ part, int tok,
                                  float* __restrict__ x,
                                  const float* __restrict__ w,
                                  const float* __restrict__ b,
                                  const float* __restrict__ ew,
                                  const float* __restrict__ eb,
                                  float* __restrict__ out_x,
                                  float* __restrict__ out_eos, float* red)
{
    int tid = threadIdx.x;
    float v[4];
    #pragma unroll
    for (int j = 0; j < 4; j++) {
        int idx = tid + 256 * j;
        float p = 0.f;
        #pragma unroll
        for (int k = 0; k < 8; k++) p += part[((size_t)(k * 32 + tok)) * E + idx];
        v[j] = x[(size_t)tok * E + idx] + p;
    }
    float mean, r;
    ln_body(v, red, &mean, &r);
    float ed = 0.f;
    #pragma unroll
    for (int j = 0; j < 4; j++) {
        int idx = tid + 256 * j;
        float y = (v[j] - mean) * r * w[idx] + b[idx];
        out_x[(size_t)tok * E + idx] = y;
        ed += y * ew[idx];
    }
    #pragma unroll
    for (int o = 16; o > 0; o >>= 1) ed += __shfl_xor_sync(0xffffffffu, ed, o);
    __syncthreads();
    if ((tid & 31) == 0) red[tid >> 5] = ed;
    __syncthreads();
    if (tid == 0)
        out_eos[tok] = red[0]+red[1]+red[2]+red[3]+red[4]+red[5]+red[6]+red[7] + eb[0];
}

// -------- attention: one block per (b,h) --------
__device__ void attn_phase(SA* sa, const float* __restrict__ q,
                           const float* __restrict__ kin,
                           const float* __restrict__ vin,
                           const float* __restrict__ kout,
                           const float* __restrict__ vout,
                           const int* __restrict__ posl,
                           float* __restrict__ outp)
{
    int bh = blockIdx.x;
    int b = bh >> 4, h = bh & 15;
    int tid = threadIdx.x;
    int pos = posl[b];
    int slen = pos + T;

    {
        int t = tid >> 6, d = tid & 63;
        sa->qs[t][d] = q[((size_t)(b * T + t)) * E + h * D + d];
    }
    __syncthreads();

    const float scale = 0.125f;
    for (int s = tid; s < slen; s += 256) {
        size_t off = ((size_t)b * L + s) * E + h * D;
        bool old = (s < pos);
        const float4* kr = (const float4*)((old ? kin : kout) + off);
        float d0 = 0.f, d1 = 0.f, d2 = 0.f, d3 = 0.f;
        #pragma unroll
        for (int i4 = 0; i4 < 16; i4++) {
            float4 kv = kr[i4];
            if (old) {
                kv.x = isnan(kv.x) ? 0.f : kv.x;
                kv.y = isnan(kv.y) ? 0.f : kv.y;
                kv.z = isnan(kv.z) ? 0.f : kv.z;
                kv.w = isnan(kv.w) ? 0.f : kv.w;
            }
            int d = i4 * 4;
            d0 += sa->qs[0][d]*kv.x + sa->qs[0][d+1]*kv.y + sa->qs[0][d+2]*kv.z + sa->qs[0][d+3]*kv.w;
            d1 += sa->qs[1][d]*kv.x + sa->qs[1][d+1]*kv.y + sa->qs[1][d+2]*kv.z + sa->qs[1][d+3]*kv.w;
            d2 += sa->qs[2][d]*kv.x + sa->qs[2][d+1]*kv.y + sa->qs[2][d+2]*kv.z + sa->qs[2][d+3]*kv.w;
            d3 += sa->qs[3][d]*kv.x + sa->qs[3][d+1]*kv.y + sa->qs[3][d+2]*kv.z + sa->qs[3][d+3]*kv.w;
        }
        sa->sc[0][s] = (s <= pos + 0) ? d0 * scale : -1e30f;
        sa->sc[1][s] = (s <= pos + 1) ? d1 * scale : -1e30f;
        sa->sc[2][s] = (s <= pos + 2) ? d2 * scale : -1e30f;
        sa->sc[3][s] = (s <= pos + 3) ? d3 * scale : -1e30f;
    }
    __syncthreads();

    #pragma unroll
    for (int t = 0; t < 4; t++) {
        float m = -1e30f;
        for (int s = tid; s < slen; s += 256) m = fmaxf(m, sa->sc[t][s]);
        #pragma unroll
        for (int o = 16; o > 0; o >>= 1) m = fmaxf(m, __shfl_xor_sync(0xffffffffu, m, o));
        if ((tid & 31) == 0) sa->red[tid >> 5] = m;
        __syncthreads();
        m = fmaxf(fmaxf(fmaxf(sa->red[0], sa->red[1]), fmaxf(sa->red[2], sa->red[3])),
                  fmaxf(fmaxf(sa->red[4], sa->red[5]), fmaxf(sa->red[6], sa->red[7])));
        float ssum = 0.f;
        for (int s = tid; s < slen; s += 256) {
            float e = __expf(sa->sc[t][s] - m);
            sa->sc[t][s] = e;
            ssum += e;
        }
        #pragma unroll
        for (int o = 16; o > 0; o >>= 1) ssum += __shfl_xor_sync(0xffffffffu, ssum, o);
        __syncthreads();
        if ((tid & 31) == 0) sa->red[tid >> 5] = ssum;
        __syncthreads();
        if (tid == 0)
            sa->inv[t] = 1.0f / (sa->red[0]+sa->red[1]+sa->red[2]+sa->red[3]
                               + sa->red[4]+sa->red[5]+sa->red[6]+sa->red[7]);
        __syncthreads();
    }

    {
        int sg = tid >> 6, d = tid & 63;
        int chunk = (slen + 3) >> 2;
        int s0 = sg * chunk;
        int s1 = min(slen, s0 + chunk);
        float a0 = 0.f, a1 = 0.f, a2 = 0.f, a3 = 0.f;
        int s = s0;
        for (; s + 2 <= s1; s += 2) {
            bool o0 = (s < pos), o1 = (s + 1 < pos);
            float v0 = (o0 ? vin : vout)[((size_t)b * L + s) * E + h * D + d];
            float v1 = (o1 ? vin : vout)[((size_t)b * L + s + 1) * E + h * D + d];
            if (o0) v0 = isnan(v0) ? 0.f : v0;
            if (o1) v1 = isnan(v1) ? 0.f : v1;
            a0 += sa->sc[0][s] * v0 + sa->sc[0][s+1] * v1;
            a1 += sa->sc[1][s] * v0 + sa->sc[1][s+1] * v1;
            a2 += sa->sc[2][s] * v0 + sa->sc[2][s+1] * v1;
            a3 += sa->sc[3][s] * v0 + sa->sc[3][s+1] * v1;
        }
        if (s < s1) {
            bool o0 = (s < pos);
            float v0 = (o0 ? vin : vout)[((size_t)b * L + s) * E + h * D + d];
            if (o0) v0 = isnan(v0) ? 0.f : v0;
            a0 += sa->sc[0][s] * v0;
            a1 += sa->sc[1][s] * v0;
            a2 += sa->sc[2][s] * v0;
            a3 += sa->sc[3][s] * v0;
        }
        sa->vpart[sg][0][d] = a0;
        sa->vpart[sg][1][d] = a1;
        sa->vpart[sg][2][d] = a2;
        sa->vpart[sg][3][d] = a3;
    }
    __syncthreads();
    {
        int t = tid >> 6, d = tid & 63;
        float sum = sa->vpart[0][t][d] + sa->vpart[1][t][d]
                  + sa->vpart[2][t][d] + sa->vpart[3][t][d];
        outp[((size_t)(b * T + t)) * E + h * D + d] = sum * sa->inv[t];
    }
}

// ======== THE MEGAKERNEL ========
__global__ __launch_bounds__(256) void mega_kernel(
    const float* __restrict__ seq, const float* __restrict__ bos,
    const float* __restrict__ caches, const int* __restrict__ positions,
    const float* __restrict__ in_w, const float* __restrict__ ip_w,
    const float* __restrict__ op_w,
    const float* __restrict__ n1w, const float* __restrict__ n1b,
    const float* __restrict__ n2w, const float* __restrict__ n2b,
    const float* __restrict__ l1w, const float* __restrict__ l2w,
    const float* __restrict__ on_w, const float* __restrict__ on_b,
    const float* __restrict__ eos_w, const float* __restrict__ eos_b,
    float* __restrict__ out_x, float* __restrict__ out_eos,
    float* __restrict__ out_cache, float* __restrict__ out_pos)
{
    __shared__ __align__(16) char smraw[SMEM_BYTES];
    SG* sg = (SG*)smraw;
    SA* sa = (SA*)smraw;
    float* red = (float*)smraw;

    const int bid = blockIdx.x;
    const int tid = threadIdx.x;
    unsigned base = g_bar_epoch;
    unsigned bc = 0;

    // ---- embed + out_pos ----
    {
        float* srow = (float*)smraw;
        int tok = bid >> 2;
        if (tid < 32) {
            float v = seq[tok * INDIM + tid];
            srow[tid] = isnan(v) ? bos[tid] : v;
        }
        __syncthreads();
        int col = ((bid & 3) << 8) + tid;
        const float4* wr = (const float4*)(in_w + (size_t)col * INDIM);
        float acc = 0.f;
        #pragma unroll
        for (int k4 = 0; k4 < 8; k4++) {
            float4 w = wr[k4];
            acc += srow[k4*4]*w.x + srow[k4*4+1]*w.y + srow[k4*4+2]*w.z + srow[k4*4+3]*w.w;
        }
        g_x[(size_t)tok * E + col] = acc;
        if (bid == NB - 1 && tid < NL * B)
            out_pos[tid] = (float)(positions[tid] + T);
    }
    gbar(base + ++bc);

    if (bid < NTOK) ln_phase(g_x + (size_t)bid * E, n1w, n1b, g_xn + (size_t)bid * E, red);
    gbar(base + ++bc);

    for (int i = 0; i < NL; i++) {
        const float* ipw = ip_w + (size_t)i * 3 * E * E;
        const float* opw = op_w + (size_t)i * E * E;
        const float* l1  = l1w  + (size_t)i * FF * E;
        const float* l2  = l2w  + (size_t)i * E * FF;
        float* kcache = out_cache + ((size_t)i * 2 + 0) * B * L * E;
        float* vcache = out_cache + ((size_t)i * 2 + 1) * B * L * E;
        const float* kcin = caches + ((size_t)i * 2 + 0) * B * L * E;
        const float* vcin = caches + ((size_t)i * 2 + 1) * B * L * E;
        const int* posl = positions + i * B;

        // qkv gemv: 48 tiles x ks2 = 96 units
        if (bid < 96) {
            int tile = bid >> 1, ks = bid & 1;
            gemv_tile<0>(g_xn, ipw, g_part2, E, 3 * E, tile * 64, ks * 512, 512, ks, sg);
        }
        gbar(base + ++bc);

        // reduce2 + rope + scatter
        for (int id = bid * 256 + tid; id < 49152; id += NB * 256) {
            int tok = id / 1536;
            int f = (id - tok * 1536) * 2;
            float s0 = g_part2[(size_t)tok * 3072 + f]     + g_part2[(size_t)(32 + tok) * 3072 + f];
            float s1 = g_part2[(size_t)tok * 3072 + f + 1] + g_part2[(size_t)(32 + tok) * 3072 + f + 1];
            int b = tok >> 2, t = tok & 3;
            int pos = posl[b];
            if (f < E) {
                int j = (f & 63) >> 1;
                float freq = __expf(-(float)j * (logf(10000.0f) / 32.0f));
                float sn, cs;
                sincosf((float)(pos + t) * freq, &sn, &cs);
                g_q[(size_t)tok * E + f]     = s0 * cs - s1 * sn;
                g_q[(size_t)tok * E + f + 1] = s0 * sn + s1 * cs;
            } else if (f < 2 * E) {
                int fk = f - E;
                int j = (fk & 63) >> 1;
                float freq = __expf(-(float)j * (logf(10000.0f) / 32.0f));
                float sn, cs;
                sincosf((float)(pos + t) * freq, &sn, &cs);
                int slot = (pos + t) % L;
                size_t off = ((size_t)b * L + slot) * E + fk;
                kcache[off]     = s0 * cs - s1 * sn;
                kcache[off + 1] = s0 * sn + s1 * cs;
            } else {
                int fv = f - 2 * E;
                int slot = (pos + t) % L;
                size_t off = ((size_t)b * L + slot) * E + fv;
                vcache[off]     = s0;
                vcache[off + 1] = s1;
            }
        }
        gbar(base + ++bc);

        attn_phase(sa, g_q, kcin, vcin, kcache, vcache, posl, g_attn);
        gbar(base + ++bc);

        // op gemv: 16 tiles x ks8 = 128 units
        {
            int tile = bid >> 3, ks = bid & 7;
            gemv_tile<0>(g_attn, opw, g_part2, E, E, tile * 64, ks * 128, 128, ks, sg);
        }
        gbar(base + ++bc);

        if (bid < NTOK)
            reduce_add_ln<8>(g_part2, bid, g_x, n2w + (size_t)i * E, n2b + (size_t)i * E, g_xn, red);
        gbar(base + ++bc);

        // l1 gemv: 64 tiles x ks2 = 128 units -> g_part
        {
            int tile = bid >> 1, ks = bid & 1;
            gemv_tile<0>(g_xn, l1, g_part, E, FF, tile * 64, ks * 512, 512, ks, sg);
        }
        gbar(base + ++bc);

        // l2 gemv: gelu fused on X load (X = l1 partial pair), 16 tiles x ks8
        {
            int tile = bid >> 3, ks = bid & 7;
            gemv_tile<1>(g_part, l2, g_part2, FF, E, tile * 64, ks * 512, 512, ks, sg);
        }
        gbar(base + ++bc);

        if (i + 1 < NL) {
            if (bid < NTOK)
                reduce_add_ln<8>(g_part2, bid, g_x,
                                 n1w + (size_t)(i + 1) * E, n1b + (size_t)(i + 1) * E,
                                 g_xn, red);
            gbar(base + ++bc);
        } else {
            if (bid < NTOK)
                reduce_add_ln_eos(g_part2, bid, g_x, on_w, on_b,
                                  eos_w, eos_b, out_x, out_eos, red);
        }
    }
}

// -------- bulk cache copy: <=32 regs so it co-resides with the megakernel --------
__global__ __launch_bounds__(256, 8) void cache_copy_kernel(
    const float4* __restrict__ in, float4* __restrict__ out,
    const int* __restrict__ allpos)
{
    long long stride = (long long)gridDim.x * 256;
    #pragma unroll 2
    for (long long i = (long long)blockIdx.x * 256 + threadIdx.x; i < CACHE_F4; i += stride) {
        unsigned slot = ((unsigned)(i >> 8)) & 2047u;
        unsigned b    = ((unsigned)(i >> 19)) & 7u;
        unsigned l    = ((unsigned)(i >> 22)) >> 1;
        int p = allpos[l * 8 + b];
        if ((unsigned)((int)slot - p) < (unsigned)T) continue;
        float4 v = in[i];
        v.x = isnan(v.x) ? 0.0f : v.x;
        v.y = isnan(v.y) ? 0.0f : v.y;
        v.z = isnan(v.z) ? 0.0f : v.z;
        v.w = isnan(v.w) ? 0.0f : v.w;
        out[i] = v;
    }
}

extern "C" void kernel_launch(void* const* d_in, const int* in_sizes, int n_in,
                              void* d_out, int out_size)
{
    const float* seq       = (const float*)d_in[0];
    const float* bos       = (const float*)d_in[1];
    const float* caches    = (const float*)d_in[2];
    const int*   positions = (const int*)  d_in[3];
    const float* in_w      = (const float*)d_in[4];
    const float* ip_w      = (const float*)d_in[5];
    const float* op_w      = (const float*)d_in[6];
    const float* n1w       = (const float*)d_in[7];
    const float* n1b       = (const float*)d_in[8];
    const float* n2w       = (const float*)d_in[9];
    const float* n2b       = (const float*)d_in[10];
    const float* l1_w      = (const float*)d_in[11];
    const float* l2_w      = (const float*)d_in[12];
    const float* on_w      = (const float*)d_in[13];
    const float* on_b      = (const float*)d_in[14];
    const float* eos_w     = (const float*)d_in[15];
    const float* eos_b     = (const float*)d_in[16];

    float* out = (float*)d_out;
    const size_t cache_elems = (size_t)NL * 2 * B * L * E;
    float* out_x     = out;
    float* out_eos   = out + (size_t)NTOK * E;
    float* out_cache = out_eos + NTOK;
    float* out_pos   = out_cache + cache_elems;

    cudaStream_t cs;
    cudaStreamCreateWithFlags(&cs, cudaStreamNonBlocking);
    cudaEvent_t evFork, evJoin;
    cudaEventCreateWithFlags(&evFork, cudaEventDisableTiming);
    cudaEventCreateWithFlags(&evJoin, cudaEventDisableTiming);

    cudaEventRecord(evFork, 0);

    // megakernel FIRST so its 128 blocks claim their SM slots
    mega_kernel<<<NB, 256>>>(seq, bos, caches, positions,
                             in_w, ip_w, op_w,
                             n1w, n1b, n2w, n2b, l1_w, l2_w,
                             on_w, on_b, eos_w, eos_b,
                             out_x, out_eos, out_cache, out_pos);

    // copy co-resides: 2 blocks/SM, <=32 regs each
    cudaStreamWaitEvent(cs, evFork, 0);
    cache_copy_kernel<<<296, 256, 0, cs>>>((const float4*)caches,
                                           (float4*)out_cache, positions);
    cudaEventRecord(evJoin, cs);

    cudaStreamWaitEvent(0, evJoin, 0);
}